// round 8
// baseline (speedup 1.0000x reference)
#include <cuda_runtime.h>
#include <cstdint>
#include <cstddef>

// ============================================================================
// W8A8B8O8 Linear, sm_103 base ISA. Hybrid two-engine GEMM:
//   - 8 tensor warps: cols [0,128)   mma.sync m16n8k32 s8 (warp tile 64x32)
//     legacy IMMA unit measured at ~243 MAC/cyc/SM (saturated)
//   - 8 dp4a warps:   cols [128,256) IDP4A on fma pipe (~256 MAC/cyc/SM cap)
// R8: rebalanced 160/96 -> 128/128 (engines measured at 243 vs >=146-with-slack)
// Both consume one 4-stage cp.async SMEM pipeline (BM=128, BN=256, BK=64).
// x/w arrive as 32-bit promoted int8; converted to packed int8 scratch first.
// ============================================================================

#define DINLINE __device__ __forceinline__

static constexpr int M_TOTAL = 8192;
static constexpr int K_TOTAL = 4096;
static constexpr int N_TOTAL = 4096;

static constexpr int BM = 128;
static constexpr int BN = 256;
static constexpr int BK = 64;
static constexpr int STAGES = 4;
static constexpr int KCHUNKS = K_TOTAL / BK;      // 64
static constexpr int NUM_M = M_TOTAL / BM;        // 64
static constexpr int NUM_N = N_TOTAL / BN;        // 16
static constexpr int GROUP_M = 8;
static constexpr int NTHREADS = 512;              // 8 tensor + 8 dp4a warps
static constexpr int TENSOR_N = 128;              // tensor cols per CTA tile

static constexpr uint32_t A_BYTES = BM * BK;                  // 8 KB
static constexpr uint32_t B_BYTES = BN * BK;                  // 16 KB
static constexpr uint32_t STAGE_BYTES = A_BYTES + B_BYTES;    // 24 KB
static constexpr uint32_t SMEM_TOTAL = STAGES * STAGE_BYTES;  // 96 KB

// int8 scratch — static __device__ globals, no allocation.
__device__ uint8_t g_x8[(size_t)M_TOTAL * K_TOTAL];   // 32 MB
__device__ uint8_t g_wT[(size_t)N_TOTAL * K_TOTAL];   // 16 MB

// Packed-tile offset: 2 logical rows per 128B smem row; 16B granule index is
// xor-swizzled with the low 3 bits of the smem row.
DINLINE uint32_t swz_addr(uint32_t row128, uint32_t gran) {
    return row128 * 128u + ((gran ^ (row128 & 7u)) << 4);
}

DINLINE uint32_t smem_u32(const void* p) {
    uint32_t r;
    asm("{ .reg .u64 t; cvta.to.shared.u64 t, %1; cvt.u32.u64 %0, t; }" : "=r"(r) : "l"(p));
    return r;
}

DINLINE void cp_async16(uint32_t saddr, const void* gaddr) {
    asm volatile("cp.async.cg.shared.global [%0], [%1], 16;" :: "r"(saddr), "l"(gaddr) : "memory");
}
DINLINE void cp_commit() { asm volatile("cp.async.commit_group;" ::: "memory"); }
DINLINE void cp_wait2() { asm volatile("cp.async.wait_group 2;" ::: "memory"); }

#define LDSM4(r, addr)                                                         \
    asm volatile("ldmatrix.sync.aligned.m8n8.x4.shared.b16 {%0,%1,%2,%3}, [%4];" \
                 : "=r"((r)[0]), "=r"((r)[1]), "=r"((r)[2]), "=r"((r)[3])      \
                 : "r"(addr))

DINLINE void mma_s8(uint32_t* c, const uint32_t* a, uint32_t b0, uint32_t b1) {
    asm volatile(
        "mma.sync.aligned.m16n8k32.row.col.s32.s8.s8.s32 "
        "{%0,%1,%2,%3}, {%4,%5,%6,%7}, {%8,%9}, {%0,%1,%2,%3};"
        : "+r"(c[0]), "+r"(c[1]), "+r"(c[2]), "+r"(c[3])
        : "r"(a[0]), "r"(a[1]), "r"(a[2]), "r"(a[3]), "r"(b0), "r"(b1));
}

DINLINE int q8(int v, float s) {
    int q = __float2int_rn((float)v * s);   // RNE matches jnp.round
    return q < -128 ? -128 : (q > 127 ? 127 : q);
}

// Auto-detect element storage: small int bit-pattern => int32 storage; else
// interpret the bits as float32 and round-to-nearest-even.
DINLINE uint32_t cvt_b(uint32_t bits) {
    int v = (int)bits;
    if (v < -128 || v > 127) v = __float2int_rn(__int_as_float(bits));
    v = v < -128 ? -128 : (v > 127 ? 127 : v);
    return (uint32_t)v & 0xFFu;
}

// ============================================================================
// x convert: 32-bit-stored values -> g_x8 int8 (same layout [M,K])
// ============================================================================
__global__ void __launch_bounds__(256) x_convert_kernel(const uint32_t* __restrict__ xin) {
    const size_t base = ((size_t)blockIdx.x * 256 + threadIdx.x) * 16;
    alignas(16) uint8_t o[16];
#pragma unroll
    for (int i = 0; i < 16; i += 4) {
        const uint4 v = *reinterpret_cast<const uint4*>(xin + base + i);
        o[i + 0] = (uint8_t)cvt_b(v.x);
        o[i + 1] = (uint8_t)cvt_b(v.y);
        o[i + 2] = (uint8_t)cvt_b(v.z);
        o[i + 3] = (uint8_t)cvt_b(v.w);
    }
    *reinterpret_cast<uint4*>(g_x8 + base) = *reinterpret_cast<const uint4*>(o);
}

// ============================================================================
// Weight convert + transpose: w[K,N] (N-contig, 32-bit stored) -> g_wT[N,K] int8
// ============================================================================
__global__ void __launch_bounds__(256) w_convert_transpose(const uint32_t* __restrict__ w) {
    __shared__ uint8_t t[64][65];
    const int tid = threadIdx.x;
    const int n0 = blockIdx.x * 64;
    const int k0 = blockIdx.y * 64;

    const int r = tid >> 2;
    const int cseg = (tid & 3) * 16;
    const uint32_t* src = w + (size_t)(k0 + r) * N_TOTAL + n0 + cseg;
#pragma unroll
    for (int i = 0; i < 16; i += 4) {
        const uint4 v = *reinterpret_cast<const uint4*>(src + i);
        t[r][cseg + i + 0] = (uint8_t)cvt_b(v.x);
        t[r][cseg + i + 1] = (uint8_t)cvt_b(v.y);
        t[r][cseg + i + 2] = (uint8_t)cvt_b(v.z);
        t[r][cseg + i + 3] = (uint8_t)cvt_b(v.w);
    }
    __syncthreads();

    const int n = tid >> 2;
    const int kseg = (tid & 3) * 16;
    alignas(16) uint8_t o[16];
#pragma unroll
    for (int j = 0; j < 16; ++j) o[j] = t[kseg + j][n];
    *reinterpret_cast<uint4*>(g_wT + (size_t)(n0 + n) * K_TOTAL + k0 + kseg) =
        *reinterpret_cast<const uint4*>(o);
}

// ============================================================================
// Hybrid GEMM kernel: tensor warps + dp4a warps
// ============================================================================
__global__ void __launch_bounds__(NTHREADS, 1)
w8a8_gemm_kernel(const float* __restrict__ ascale,
                 const float* __restrict__ bscale,
                 float* __restrict__ out) {
    extern __shared__ __align__(1024) uint8_t smem_raw[];
    const uint32_t smem = smem_u32(smem_raw);
    const int t = threadIdx.x;
    const int lane = t & 31;
    const int warp = t >> 5;

    // --- M-grouped raster: W tiles stay L2-resident while A streams ---
    const int bid = blockIdx.x;
    const int group_sz = GROUP_M * NUM_N;
    const int gid = bid / group_sz;
    const int within = bid - gid * group_sz;
    const int pid_m = gid * GROUP_M + (within % GROUP_M);
    const int pid_n = within / GROUP_M;
    const int m0 = pid_m * BM;
    const int n0 = pid_n * BN;

    // --- producers: 3 x 16B granules per thread per stage ---
    uint32_t aS; const uint8_t* aG;
    {
        const int m = t >> 2, k16 = t & 3;
        aS = smem + swz_addr(m >> 1, (m & 1) * 4 + k16);
        aG = g_x8 + (size_t)(m0 + m) * K_TOTAL + k16 * 16;
    }
    uint32_t bS[2]; const uint8_t* bG[2];
#pragma unroll
    for (int i = 0; i < 2; ++i) {
        const int q = t + i * NTHREADS;            // 0..1023
        const int n = q >> 2, k16 = q & 3;
        bS[i] = smem + A_BYTES + swz_addr(n >> 1, (n & 1) * 4 + k16);
        bG[i] = g_wT + (size_t)(n0 + n) * K_TOTAL + k16 * 16;
    }

    auto load_stage = [&](int s, int chunk) {
        const uint32_t so = s * STAGE_BYTES;
        const size_t ko = (size_t)chunk * BK;
        cp_async16(aS + so, aG + ko);
#pragma unroll
        for (int i = 0; i < 2; ++i) cp_async16(bS[i] + so, bG[i] + ko);
    };

    const float scl = ascale[0] * bscale[0];

    // --- prologue ---
#pragma unroll
    for (int s = 0; s < STAGES - 1; ++s) { load_stage(s, s); cp_commit(); }

    if (warp < 8) {
        // ================= tensor engine: cols [0, 128) =================
        const int wm = warp >> 2;   // 0..1 (64 rows)
        const int wn = warp & 3;    // 0..3 (32 cols each)

        // A x4 (PTX ISA a0..a3): m0=r0-7 klo, m1=r8-15 klo, m2=r0-7 khi, m3=r8-15 khi
        uint32_t aOff, bOff;
        {
            const int mlocal = ((lane >> 3) & 1) * 8 + (lane & 7);
            const int k16a = lane >> 4;
            const int am = wm * 64 + mlocal;
            aOff = swz_addr(am >> 1, (am & 1) * 4 + k16a);
            const int j = lane >> 3;
            const int nlocal = (j >> 1) * 8 + (lane & 7);
            const int k16b = j & 1;
            const int bn = wn * 32 + nlocal;
            bOff = A_BYTES + swz_addr(bn >> 1, (bn & 1) * 4 + k16b);
        }

        uint32_t acc[4][4][4];
#pragma unroll
        for (int mt = 0; mt < 4; ++mt)
#pragma unroll
            for (int nt = 0; nt < 4; ++nt)
#pragma unroll
                for (int r = 0; r < 4; ++r) acc[mt][nt][r] = 0;

        for (int c = 0; c < KCHUNKS; ++c) {
            cp_wait2();
            __syncthreads();
            if (c + STAGES - 1 < KCHUNKS)
                load_stage((c + STAGES - 1) & (STAGES - 1), c + STAGES - 1);
            cp_commit();

            const uint32_t so = (uint32_t)(c & (STAGES - 1)) * STAGE_BYTES;
#pragma unroll
            for (int kp = 0; kp < 2; ++kp) {
                const uint32_t kx = (uint32_t)kp << 5;
                uint32_t av[4][4];
#pragma unroll
                for (int mt = 0; mt < 4; ++mt) {
                    const uint32_t ad = smem + ((aOff + so + mt * 1024u) ^ kx);
                    LDSM4(av[mt], ad);
                }
                uint32_t bv[2][4];
#pragma unroll
                for (int nt2 = 0; nt2 < 2; ++nt2) {
                    const uint32_t bd = smem + ((bOff + so + nt2 * 1024u) ^ kx);
                    LDSM4(bv[nt2], bd);
                }
#pragma unroll
                for (int mt = 0; mt < 4; ++mt)
#pragma unroll
                    for (int nt = 0; nt < 4; ++nt) {
                        const uint32_t* bp = &bv[nt >> 1][(nt & 1) * 2];
                        mma_s8(acc[mt][nt], av[mt], bp[0], bp[1]);
                    }
            }
        }

        // epilogue (tensor)
#pragma unroll
        for (int mt = 0; mt < 4; ++mt) {
#pragma unroll
            for (int nt = 0; nt < 4; ++nt) {
                const int row = m0 + wm * 64 + mt * 16 + (lane >> 2);
                const int col = n0 + wn * 32 + nt * 8 + 2 * (lane & 3);
                const int* a4 = reinterpret_cast<const int*>(acc[mt][nt]);
                float2 v0, v1;
                v0.x = (float)q8(a4[0], scl);
                v0.y = (float)q8(a4[1], scl);
                v1.x = (float)q8(a4[2], scl);
                v1.y = (float)q8(a4[3], scl);
                *reinterpret_cast<float2*>(out + (size_t)row * N_TOTAL + col) = v0;
                *reinterpret_cast<float2*>(out + (size_t)(row + 8) * N_TOTAL + col) = v1;
            }
        }
    } else {
        // ================= dp4a engine: cols [128, 256) =================
        const int dw = warp - 8;
        const int r0 = (dw & 3) * 32;               // 4 row-quads of 32
        const int c0 = TENSOR_N + (dw >> 2) * 64;   // 2 col-halves of 64
        const int tr = lane >> 3;                   // 0..3 -> 8-row group
        const int tc = lane & 7;                    // 0..7 -> 8-col group

        uint32_t aoffs[8], boffs[8];
        uint32_t as3[8], bs3[8];
#pragma unroll
        for (int i = 0; i < 8; ++i) {
            const int r = r0 + tr * 8 + i;
            const uint32_t r128 = (uint32_t)r >> 1;
            const uint32_t s = r128 & 7u;
            const uint32_t gb = (uint32_t)(r & 1) * 4u;
            aoffs[i] = r128 * 128u + ((gb ^ (s & 4u)) << 4);
            as3[i] = s & 3u;
        }
#pragma unroll
        for (int j = 0; j < 8; ++j) {
            const int n = c0 + tc * 8 + j;
            const uint32_t n128 = (uint32_t)n >> 1;
            const uint32_t s = n128 & 7u;
            const uint32_t gb = (uint32_t)(n & 1) * 4u;
            boffs[j] = A_BYTES + n128 * 128u + ((gb ^ (s & 4u)) << 4);
            bs3[j] = s & 3u;
        }

        int accd[8][8];
#pragma unroll
        for (int i = 0; i < 8; ++i)
#pragma unroll
            for (int j = 0; j < 8; ++j) accd[i][j] = 0;

        for (int c = 0; c < KCHUNKS; ++c) {
            cp_wait2();
            __syncthreads();
            if (c + STAGES - 1 < KCHUNKS)
                load_stage((c + STAGES - 1) & (STAGES - 1), c + STAGES - 1);
            cp_commit();

            const uint32_t so = (uint32_t)(c & (STAGES - 1)) * STAGE_BYTES;
#pragma unroll
            for (int g = 0; g < 4; ++g) {   // logical 16B k-granule
                uint4 br[8];
#pragma unroll
                for (int j = 0; j < 8; ++j)
                    br[j] = *reinterpret_cast<const uint4*>(
                        smem_raw + so + boffs[j] + (((uint32_t)g ^ bs3[j]) << 4));
#pragma unroll
                for (int ih = 0; ih < 2; ++ih) {
                    uint4 ar[4];
#pragma unroll
                    for (int ii = 0; ii < 4; ++ii) {
                        const int i = ih * 4 + ii;
                        ar[ii] = *reinterpret_cast<const uint4*>(
                            smem_raw + so + aoffs[i] + (((uint32_t)g ^ as3[i]) << 4));
                    }
#pragma unroll
                    for (int ii = 0; ii < 4; ++ii)
#pragma unroll
                        for (int j = 0; j < 8; ++j) {
                            int& a = accd[ih * 4 + ii][j];
                            a = __dp4a((int)ar[ii].x, (int)br[j].x, a);
                            a = __dp4a((int)ar[ii].y, (int)br[j].y, a);
                            a = __dp4a((int)ar[ii].z, (int)br[j].z, a);
                            a = __dp4a((int)ar[ii].w, (int)br[j].w, a);
                        }
                }
            }
        }

        // epilogue (dp4a)
#pragma unroll
        for (int i = 0; i < 8; ++i) {
            const int row = m0 + r0 + tr * 8 + i;
            const int colb = n0 + c0 + tc * 8;
#pragma unroll
            for (int jp = 0; jp < 4; ++jp) {
                float2 v;
                v.x = (float)q8(accd[i][2 * jp + 0], scl);
                v.y = (float)q8(accd[i][2 * jp + 1], scl);
                *reinterpret_cast<float2*>(out + (size_t)row * N_TOTAL + colb + 2 * jp) = v;
            }
        }
    }
}

// ============================================================================
// Launch — identify inputs by element count (robust to metadata ordering)
// ============================================================================
extern "C" void kernel_launch(void* const* d_in, const int* in_sizes, int n_in,
                              void* d_out, int out_size) {
    (void)out_size;
    const uint32_t* x = nullptr;
    const uint32_t* w = nullptr;
    const float* s1 = nullptr;
    const float* s2 = nullptr;
    for (int i = 0; i < n_in; ++i) {
        const long sz = in_sizes[i];
        if (sz == (long)M_TOTAL * K_TOTAL) x = (const uint32_t*)d_in[i];
        else if (sz == (long)K_TOTAL * N_TOTAL) w = (const uint32_t*)d_in[i];
        else if (sz == 1) { if (!s1) s1 = (const float*)d_in[i]; else s2 = (const float*)d_in[i]; }
    }
    if (!x || !w || !s1 || !s2) return;

    cudaFuncSetAttribute(w8a8_gemm_kernel,
                         cudaFuncAttributeMaxDynamicSharedMemorySize, (int)SMEM_TOTAL);

    x_convert_kernel<<<(M_TOTAL * K_TOTAL) / (256 * 16), 256>>>(x);
    w_convert_transpose<<<dim3(N_TOTAL / 64, K_TOTAL / 64), 256>>>(w);
    w8a8_gemm_kernel<<<NUM_M * NUM_N, NTHREADS, SMEM_TOTAL>>>(s1, s2, (float*)d_out);
}

// round 9
// speedup vs baseline: 1.3210x; 1.3210x over previous
#include <cuda_runtime.h>
#include <cstdint>
#include <cstddef>

// ============================================================================
// W8A8B8O8 Linear, sm_103 base ISA. Hybrid two-engine GEMM (R7 optimum split):
//   - 8 tensor warps: cols [0,160)   mma.sync m16n8k32 s8 (~243 MAC/cyc/SM)
//   - 8 dp4a warps:   cols [160,256) IDP4A on fma pipe   (~145 MAC/cyc/SM)
// R9: BK 64->128 with 3 stages (halves barrier count; amortizes sync overhead),
//     converts fused into ONE prep kernel (2 launches total -> GEMM gets ncu'd).
// BM=128, BN=256, BK=128, stage=48KB, SMEM=144KB, 512 threads.
// ============================================================================

#define DINLINE __device__ __forceinline__

static constexpr int M_TOTAL = 8192;
static constexpr int K_TOTAL = 4096;
static constexpr int N_TOTAL = 4096;

static constexpr int BM = 128;
static constexpr int BN = 256;
static constexpr int BK = 128;
static constexpr int STAGES = 3;
static constexpr int KCHUNKS = K_TOTAL / BK;      // 32
static constexpr int NUM_M = M_TOTAL / BM;        // 64
static constexpr int NUM_N = N_TOTAL / BN;        // 16
static constexpr int GROUP_M = 8;
static constexpr int NTHREADS = 512;              // 8 tensor + 8 dp4a warps
static constexpr int TENSOR_N = 160;

static constexpr uint32_t A_BYTES = BM * BK;                  // 16 KB
static constexpr uint32_t B_BYTES = BN * BK;                  // 32 KB
static constexpr uint32_t STAGE_BYTES = A_BYTES + B_BYTES;    // 48 KB
static constexpr uint32_t SMEM_TOTAL = STAGES * STAGE_BYTES;  // 144 KB

// int8 scratch — static __device__ globals, no allocation.
__device__ uint8_t g_x8[(size_t)M_TOTAL * K_TOTAL];   // 32 MB
__device__ uint8_t g_wT[(size_t)N_TOTAL * K_TOTAL];   // 16 MB

// Unpacked tile: one logical row per 128B smem row; 16B granule xor-swizzled
// with the low 3 bits of the row.
DINLINE uint32_t swz_addr(uint32_t row, uint32_t gran) {
    return row * 128u + ((gran ^ (row & 7u)) << 4);
}

DINLINE uint32_t smem_u32(const void* p) {
    uint32_t r;
    asm("{ .reg .u64 t; cvta.to.shared.u64 t, %1; cvt.u32.u64 %0, t; }" : "=r"(r) : "l"(p));
    return r;
}

DINLINE void cp_async16(uint32_t saddr, const void* gaddr) {
    asm volatile("cp.async.cg.shared.global [%0], [%1], 16;" :: "r"(saddr), "l"(gaddr) : "memory");
}
DINLINE void cp_commit() { asm volatile("cp.async.commit_group;" ::: "memory"); }
DINLINE void cp_wait1() { asm volatile("cp.async.wait_group 1;" ::: "memory"); }

#define LDSM4(r, addr)                                                         \
    asm volatile("ldmatrix.sync.aligned.m8n8.x4.shared.b16 {%0,%1,%2,%3}, [%4];" \
                 : "=r"((r)[0]), "=r"((r)[1]), "=r"((r)[2]), "=r"((r)[3])      \
                 : "r"(addr))

DINLINE void mma_s8(uint32_t* c, const uint32_t* a, uint32_t b0, uint32_t b1) {
    asm volatile(
        "mma.sync.aligned.m16n8k32.row.col.s32.s8.s8.s32 "
        "{%0,%1,%2,%3}, {%4,%5,%6,%7}, {%8,%9}, {%0,%1,%2,%3};"
        : "+r"(c[0]), "+r"(c[1]), "+r"(c[2]), "+r"(c[3])
        : "r"(a[0]), "r"(a[1]), "r"(a[2]), "r"(a[3]), "r"(b0), "r"(b1));
}

DINLINE int q8(int v, float s) {
    int q = __float2int_rn((float)v * s);   // RNE matches jnp.round
    return q < -128 ? -128 : (q > 127 ? 127 : q);
}

// Auto-detect element storage: small int bit-pattern => int32 storage; else
// interpret the bits as float32 and round-to-nearest-even.
DINLINE uint32_t cvt_b(uint32_t bits) {
    int v = (int)bits;
    if (v < -128 || v > 127) v = __float2int_rn(__int_as_float(bits));
    v = v < -128 ? -128 : (v > 127 ? 127 : v);
    return (uint32_t)v & 0xFFu;
}

// ============================================================================
// Fused prep: blocks [0,8192) convert x -> g_x8; blocks [8192,12288)
// convert+transpose w[K,N] -> g_wT[N,K].
// ============================================================================
__global__ void __launch_bounds__(256) prep_kernel(const uint32_t* __restrict__ xin,
                                                   const uint32_t* __restrict__ w) {
    if (blockIdx.x < 8192) {
        const size_t base = ((size_t)blockIdx.x * 256 + threadIdx.x) * 16;
        alignas(16) uint8_t o[16];
#pragma unroll
        for (int i = 0; i < 16; i += 4) {
            const uint4 v = *reinterpret_cast<const uint4*>(xin + base + i);
            o[i + 0] = (uint8_t)cvt_b(v.x);
            o[i + 1] = (uint8_t)cvt_b(v.y);
            o[i + 2] = (uint8_t)cvt_b(v.z);
            o[i + 3] = (uint8_t)cvt_b(v.w);
        }
        *reinterpret_cast<uint4*>(g_x8 + base) = *reinterpret_cast<const uint4*>(o);
    } else {
        __shared__ uint8_t t[64][65];
        const int bid2 = blockIdx.x - 8192;
        const int tid = threadIdx.x;
        const int n0 = (bid2 & 63) * 64;
        const int k0 = (bid2 >> 6) * 64;

        const int r = tid >> 2;
        const int cseg = (tid & 3) * 16;
        const uint32_t* src = w + (size_t)(k0 + r) * N_TOTAL + n0 + cseg;
#pragma unroll
        for (int i = 0; i < 16; i += 4) {
            const uint4 v = *reinterpret_cast<const uint4*>(src + i);
            t[r][cseg + i + 0] = (uint8_t)cvt_b(v.x);
            t[r][cseg + i + 1] = (uint8_t)cvt_b(v.y);
            t[r][cseg + i + 2] = (uint8_t)cvt_b(v.z);
            t[r][cseg + i + 3] = (uint8_t)cvt_b(v.w);
        }
        __syncthreads();

        const int n = tid >> 2;
        const int kseg = (tid & 3) * 16;
        alignas(16) uint8_t o[16];
#pragma unroll
        for (int j = 0; j < 16; ++j) o[j] = t[kseg + j][n];
        *reinterpret_cast<uint4*>(g_wT + (size_t)(n0 + n) * K_TOTAL + k0 + kseg) =
            *reinterpret_cast<const uint4*>(o);
    }
}

// ============================================================================
// Hybrid GEMM kernel: tensor warps + dp4a warps
// ============================================================================
__global__ void __launch_bounds__(NTHREADS, 1)
w8a8_gemm_kernel(const float* __restrict__ ascale,
                 const float* __restrict__ bscale,
                 float* __restrict__ out) {
    extern __shared__ __align__(1024) uint8_t smem_raw[];
    const uint32_t smem = smem_u32(smem_raw);
    const int t = threadIdx.x;
    const int lane = t & 31;
    const int warp = t >> 5;

    // --- M-grouped raster: W tiles stay L2-resident while A streams ---
    const int bid = blockIdx.x;
    const int group_sz = GROUP_M * NUM_N;
    const int gid = bid / group_sz;
    const int within = bid - gid * group_sz;
    const int pid_m = gid * GROUP_M + (within % GROUP_M);
    const int pid_n = within / GROUP_M;
    const int m0 = pid_m * BM;
    const int n0 = pid_n * BN;

    // --- producers: A 2 granules + B 4 granules per thread per stage ---
    uint32_t aS[2]; const uint8_t* aG[2];
#pragma unroll
    for (int i = 0; i < 2; ++i) {
        const int q = t + i * NTHREADS;            // 0..1023
        const int m = q >> 3, g = q & 7;
        aS[i] = smem + swz_addr(m, g);
        aG[i] = g_x8 + (size_t)(m0 + m) * K_TOTAL + g * 16;
    }
    uint32_t bS[4]; const uint8_t* bG[4];
#pragma unroll
    for (int i = 0; i < 4; ++i) {
        const int q = t + i * NTHREADS;            // 0..2047
        const int n = q >> 3, g = q & 7;
        bS[i] = smem + A_BYTES + swz_addr(n, g);
        bG[i] = g_wT + (size_t)(n0 + n) * K_TOTAL + g * 16;
    }

    auto load_stage = [&](int s, int chunk) {
        const uint32_t so = s * STAGE_BYTES;
        const size_t ko = (size_t)chunk * BK;
#pragma unroll
        for (int i = 0; i < 2; ++i) cp_async16(aS[i] + so, aG[i] + ko);
#pragma unroll
        for (int i = 0; i < 4; ++i) cp_async16(bS[i] + so, bG[i] + ko);
    };

    const float scl = ascale[0] * bscale[0];

    // --- prologue: stages 0,1 ---
#pragma unroll
    for (int s = 0; s < STAGES - 1; ++s) { load_stage(s, s); cp_commit(); }

    if (warp < 8) {
        // ================= tensor engine: cols [0, 160) =================
        const int wm = warp >> 2;   // 0..1 (64 rows)
        const int wn = warp & 3;    // 0..3 (40 cols each)

        // A x4 (PTX ISA a0..a3): m0=r0-7 klo, m1=r8-15 klo, m2=r0-7 khi, m3=r8-15 khi
        uint32_t aOff, bOff;
        {
            const int mlocal = ((lane >> 3) & 1) * 8 + (lane & 7);
            const int k16a = lane >> 4;                    // granule bit0
            const int am = wm * 64 + mlocal;
            aOff = swz_addr((uint32_t)am, (uint32_t)k16a);
            const int j = lane >> 3;
            const int nlocal = (j >> 1) * 8 + (lane & 7);
            const int k16b = j & 1;
            const int bn = wn * 40 + nlocal;
            bOff = A_BYTES + swz_addr((uint32_t)bn, (uint32_t)k16b);
        }

        uint32_t acc[4][5][4];
#pragma unroll
        for (int mt = 0; mt < 4; ++mt)
#pragma unroll
            for (int nt = 0; nt < 5; ++nt)
#pragma unroll
                for (int r = 0; r < 4; ++r) acc[mt][nt][r] = 0;

        for (int c = 0; c < KCHUNKS; ++c) {
            cp_wait1();
            __syncthreads();
            if (c + STAGES - 1 < KCHUNKS) {
                int s = (c + STAGES - 1) % STAGES;
                load_stage(s, c + STAGES - 1);
            }
            cp_commit();

            const uint32_t so = (uint32_t)(c % STAGES) * STAGE_BYTES;
#pragma unroll
            for (int kp = 0; kp < 4; ++kp) {               // 4 x k32
                const uint32_t kx = (uint32_t)kp << 5;     // granule bits 1-2
                uint32_t av[4][4];
#pragma unroll
                for (int mt = 0; mt < 4; ++mt) {
                    const uint32_t ad = smem + ((aOff + so + mt * 2048u) ^ kx);
                    LDSM4(av[mt], ad);
                }
                uint32_t bv[3][4];
#pragma unroll
                for (int nt2 = 0; nt2 < 3; ++nt2) {
                    const uint32_t bd = smem + ((bOff + so + nt2 * 2048u) ^ kx);
                    LDSM4(bv[nt2], bd);
                }
#pragma unroll
                for (int mt = 0; mt < 4; ++mt)
#pragma unroll
                    for (int nt = 0; nt < 5; ++nt) {
                        const uint32_t* bp = &bv[nt >> 1][(nt & 1) * 2];
                        mma_s8(acc[mt][nt], av[mt], bp[0], bp[1]);
                    }
            }
        }

        // epilogue (tensor)
#pragma unroll
        for (int mt = 0; mt < 4; ++mt) {
#pragma unroll
            for (int nt = 0; nt < 5; ++nt) {
                const int row = m0 + wm * 64 + mt * 16 + (lane >> 2);
                const int col = n0 + wn * 40 + nt * 8 + 2 * (lane & 3);
                const int* a4 = reinterpret_cast<const int*>(acc[mt][nt]);
                float2 v0, v1;
                v0.x = (float)q8(a4[0], scl);
                v0.y = (float)q8(a4[1], scl);
                v1.x = (float)q8(a4[2], scl);
                v1.y = (float)q8(a4[3], scl);
                *reinterpret_cast<float2*>(out + (size_t)row * N_TOTAL + col) = v0;
                *reinterpret_cast<float2*>(out + (size_t)(row + 8) * N_TOTAL + col) = v1;
            }
        }
    } else {
        // ================= dp4a engine: cols [160, 256) =================
        const int dw = warp - 8;
        const int r0 = (dw & 3) * 32;               // 4 row-quads of 32
        const int c0 = TENSOR_N + (dw >> 2) * 48;   // 2 col-halves of 48
        const int tr = lane >> 3;                   // 0..3 -> 8-row group
        const int tc = lane & 7;                    // 0..7 -> 6-col group

        uint32_t abase[8], bbase[6];
        uint32_t as7[8], bs7[6];
#pragma unroll
        for (int i = 0; i < 8; ++i) {
            const int r = r0 + tr * 8 + i;
            abase[i] = (uint32_t)r * 128u;
            as7[i] = (uint32_t)r & 7u;
        }
#pragma unroll
        for (int j = 0; j < 6; ++j) {
            const int n = c0 + tc * 6 + j;
            bbase[j] = A_BYTES + (uint32_t)n * 128u;
            bs7[j] = (uint32_t)n & 7u;
        }

        int accd[8][6];
#pragma unroll
        for (int i = 0; i < 8; ++i)
#pragma unroll
            for (int j = 0; j < 6; ++j) accd[i][j] = 0;

        for (int c = 0; c < KCHUNKS; ++c) {
            cp_wait1();
            __syncthreads();
            if (c + STAGES - 1 < KCHUNKS) {
                int s = (c + STAGES - 1) % STAGES;
                load_stage(s, c + STAGES - 1);
            }
            cp_commit();

            const uint32_t so = (uint32_t)(c % STAGES) * STAGE_BYTES;
#pragma unroll
            for (int g = 0; g < 8; ++g) {   // 8 x 16B k-granules
                uint4 br[6];
#pragma unroll
                for (int j = 0; j < 6; ++j)
                    br[j] = *reinterpret_cast<const uint4*>(
                        smem_raw + so + bbase[j] + ((((uint32_t)g ^ bs7[j])) << 4));
#pragma unroll
                for (int ih = 0; ih < 2; ++ih) {
                    uint4 ar[4];
#pragma unroll
                    for (int ii = 0; ii < 4; ++ii) {
                        const int i = ih * 4 + ii;
                        ar[ii] = *reinterpret_cast<const uint4*>(
                            smem_raw + so + abase[i] + ((((uint32_t)g ^ as7[i])) << 4));
                    }
#pragma unroll
                    for (int ii = 0; ii < 4; ++ii)
#pragma unroll
                        for (int j = 0; j < 6; ++j) {
                            int& a = accd[ih * 4 + ii][j];
                            a = __dp4a((int)ar[ii].x, (int)br[j].x, a);
                            a = __dp4a((int)ar[ii].y, (int)br[j].y, a);
                            a = __dp4a((int)ar[ii].z, (int)br[j].z, a);
                            a = __dp4a((int)ar[ii].w, (int)br[j].w, a);
                        }
                }
            }
        }

        // epilogue (dp4a)
#pragma unroll
        for (int i = 0; i < 8; ++i) {
            const int row = m0 + r0 + tr * 8 + i;
            const int colb = n0 + c0 + tc * 6;
#pragma unroll
            for (int jp = 0; jp < 3; ++jp) {
                float2 v;
                v.x = (float)q8(accd[i][2 * jp + 0], scl);
                v.y = (float)q8(accd[i][2 * jp + 1], scl);
                *reinterpret_cast<float2*>(out + (size_t)row * N_TOTAL + colb + 2 * jp) = v;
            }
        }
    }
}

// ============================================================================
// Launch — identify inputs by element count (robust to metadata ordering)
// ============================================================================
extern "C" void kernel_launch(void* const* d_in, const int* in_sizes, int n_in,
                              void* d_out, int out_size) {
    (void)out_size;
    const uint32_t* x = nullptr;
    const uint32_t* w = nullptr;
    const float* s1 = nullptr;
    const float* s2 = nullptr;
    for (int i = 0; i < n_in; ++i) {
        const long sz = in_sizes[i];
        if (sz == (long)M_TOTAL * K_TOTAL) x = (const uint32_t*)d_in[i];
        else if (sz == (long)K_TOTAL * N_TOTAL) w = (const uint32_t*)d_in[i];
        else if (sz == 1) { if (!s1) s1 = (const float*)d_in[i]; else s2 = (const float*)d_in[i]; }
    }
    if (!x || !w || !s1 || !s2) return;

    cudaFuncSetAttribute(w8a8_gemm_kernel,
                         cudaFuncAttributeMaxDynamicSharedMemorySize, (int)SMEM_TOTAL);

    prep_kernel<<<8192 + 4096, 256>>>(x, w);
    w8a8_gemm_kernel<<<NUM_M * NUM_N, NTHREADS, SMEM_TOTAL>>>(s1, s2, (float*)d_out);
}

// round 10
// speedup vs baseline: 1.3660x; 1.0341x over previous
#include <cuda_runtime.h>
#include <cstdint>
#include <cstddef>

// ============================================================================
// W8A8B8O8 Linear, sm_103 base ISA. Hybrid two-engine GEMM.
// R10: 2 CTAs/SM (256 thr, BM=128 BN=128, 96KB smem, launch_bounds(256,2))
//      so a second independent instruction stream fills tensor-unit gaps;
//      tensor warps moved to HIGH wid (4-7) for hi-wid-first issue priority.
//   - tensor warps (wid 4-7): cols [0,80)  mma.sync m16n8k32 (warp 64x40)
//   - dp4a  warps (wid 0-3): cols [80,128) IDP4A (warp 32x48, thread 8x6)
// BK=128, 3 stages. x/w converted to packed int8 scratch by one prep kernel.
// ============================================================================

#define DINLINE __device__ __forceinline__

static constexpr int M_TOTAL = 8192;
static constexpr int K_TOTAL = 4096;
static constexpr int N_TOTAL = 4096;

static constexpr int BM = 128;
static constexpr int BN = 128;
static constexpr int BK = 128;
static constexpr int STAGES = 3;
static constexpr int KCHUNKS = K_TOTAL / BK;      // 32
static constexpr int NUM_M = M_TOTAL / BM;        // 64
static constexpr int NUM_N = N_TOTAL / BN;        // 32
static constexpr int GROUP_M = 8;
static constexpr int NTHREADS = 256;              // 4 dp4a + 4 tensor warps
static constexpr int TENSOR_N = 80;               // tensor cols per CTA tile

static constexpr uint32_t A_BYTES = BM * BK;                  // 16 KB
static constexpr uint32_t B_BYTES = BN * BK;                  // 16 KB
static constexpr uint32_t STAGE_BYTES = A_BYTES + B_BYTES;    // 32 KB
static constexpr uint32_t SMEM_TOTAL = STAGES * STAGE_BYTES;  // 96 KB

// int8 scratch — static __device__ globals, no allocation.
__device__ uint8_t g_x8[(size_t)M_TOTAL * K_TOTAL];   // 32 MB
__device__ uint8_t g_wT[(size_t)N_TOTAL * K_TOTAL];   // 16 MB

// One logical row per 128B smem row; 16B granule xor-swizzled with row low bits.
DINLINE uint32_t swz_addr(uint32_t row, uint32_t gran) {
    return row * 128u + ((gran ^ (row & 7u)) << 4);
}

DINLINE uint32_t smem_u32(const void* p) {
    uint32_t r;
    asm("{ .reg .u64 t; cvta.to.shared.u64 t, %1; cvt.u32.u64 %0, t; }" : "=r"(r) : "l"(p));
    return r;
}

DINLINE void cp_async16(uint32_t saddr, const void* gaddr) {
    asm volatile("cp.async.cg.shared.global [%0], [%1], 16;" :: "r"(saddr), "l"(gaddr) : "memory");
}
DINLINE void cp_commit() { asm volatile("cp.async.commit_group;" ::: "memory"); }
DINLINE void cp_wait1() { asm volatile("cp.async.wait_group 1;" ::: "memory"); }

#define LDSM4(r, addr)                                                         \
    asm volatile("ldmatrix.sync.aligned.m8n8.x4.shared.b16 {%0,%1,%2,%3}, [%4];" \
                 : "=r"((r)[0]), "=r"((r)[1]), "=r"((r)[2]), "=r"((r)[3])      \
                 : "r"(addr))

DINLINE void mma_s8(uint32_t* c, const uint32_t* a, uint32_t b0, uint32_t b1) {
    asm volatile(
        "mma.sync.aligned.m16n8k32.row.col.s32.s8.s8.s32 "
        "{%0,%1,%2,%3}, {%4,%5,%6,%7}, {%8,%9}, {%0,%1,%2,%3};"
        : "+r"(c[0]), "+r"(c[1]), "+r"(c[2]), "+r"(c[3])
        : "r"(a[0]), "r"(a[1]), "r"(a[2]), "r"(a[3]), "r"(b0), "r"(b1));
}

DINLINE int q8(int v, float s) {
    int q = __float2int_rn((float)v * s);   // RNE matches jnp.round
    return q < -128 ? -128 : (q > 127 ? 127 : q);
}

// Auto-detect element storage: small int bit-pattern => int32 storage; else
// interpret the bits as float32 and round-to-nearest-even.
DINLINE uint32_t cvt_b(uint32_t bits) {
    int v = (int)bits;
    if (v < -128 || v > 127) v = __float2int_rn(__int_as_float(bits));
    v = v < -128 ? -128 : (v > 127 ? 127 : v);
    return (uint32_t)v & 0xFFu;
}

// ============================================================================
// Fused prep: blocks [0,8192) convert x -> g_x8; blocks [8192,12288)
// convert+transpose w[K,N] -> g_wT[N,K].
// ============================================================================
__global__ void __launch_bounds__(256) prep_kernel(const uint32_t* __restrict__ xin,
                                                   const uint32_t* __restrict__ w) {
    if (blockIdx.x < 8192) {
        const size_t base = ((size_t)blockIdx.x * 256 + threadIdx.x) * 16;
        alignas(16) uint8_t o[16];
#pragma unroll
        for (int i = 0; i < 16; i += 4) {
            const uint4 v = *reinterpret_cast<const uint4*>(xin + base + i);
            o[i + 0] = (uint8_t)cvt_b(v.x);
            o[i + 1] = (uint8_t)cvt_b(v.y);
            o[i + 2] = (uint8_t)cvt_b(v.z);
            o[i + 3] = (uint8_t)cvt_b(v.w);
        }
        *reinterpret_cast<uint4*>(g_x8 + base) = *reinterpret_cast<const uint4*>(o);
    } else {
        __shared__ uint8_t t[64][65];
        const int bid2 = blockIdx.x - 8192;
        const int tid = threadIdx.x;
        const int n0 = (bid2 & 63) * 64;
        const int k0 = (bid2 >> 6) * 64;

        const int r = tid >> 2;
        const int cseg = (tid & 3) * 16;
        const uint32_t* src = w + (size_t)(k0 + r) * N_TOTAL + n0 + cseg;
#pragma unroll
        for (int i = 0; i < 16; i += 4) {
            const uint4 v = *reinterpret_cast<const uint4*>(src + i);
            t[r][cseg + i + 0] = (uint8_t)cvt_b(v.x);
            t[r][cseg + i + 1] = (uint8_t)cvt_b(v.y);
            t[r][cseg + i + 2] = (uint8_t)cvt_b(v.z);
            t[r][cseg + i + 3] = (uint8_t)cvt_b(v.w);
        }
        __syncthreads();

        const int n = tid >> 2;
        const int kseg = (tid & 3) * 16;
        alignas(16) uint8_t o[16];
#pragma unroll
        for (int j = 0; j < 16; ++j) o[j] = t[kseg + j][n];
        *reinterpret_cast<uint4*>(g_wT + (size_t)(n0 + n) * K_TOTAL + k0 + kseg) =
            *reinterpret_cast<const uint4*>(o);
    }
}

// ============================================================================
// Hybrid GEMM kernel: 2 CTAs/SM, tensor warps (hi wid) + dp4a warps (lo wid)
// ============================================================================
__global__ void __launch_bounds__(NTHREADS, 2)
w8a8_gemm_kernel(const float* __restrict__ ascale,
                 const float* __restrict__ bscale,
                 float* __restrict__ out) {
    extern __shared__ __align__(1024) uint8_t smem_raw[];
    const uint32_t smem = smem_u32(smem_raw);
    const int t = threadIdx.x;
    const int lane = t & 31;
    const int warp = t >> 5;

    // --- M-grouped raster: W tiles stay L2-resident while A streams ---
    const int bid = blockIdx.x;
    const int group_sz = GROUP_M * NUM_N;          // 256
    const int gid = bid / group_sz;
    const int within = bid - gid * group_sz;
    const int pid_m = gid * GROUP_M + (within % GROUP_M);
    const int pid_n = within / GROUP_M;
    const int m0 = pid_m * BM;
    const int n0 = pid_n * BN;

    // --- producers: A 4 granules + B 4 granules per thread per stage ---
    // base granule: q = t, derived granules at q + i*256 (row += 32).
    uint32_t aS0, bS0;
    const uint8_t *aG0, *bG0;
    {
        const int m = t >> 3, g = t & 7;
        aS0 = smem + swz_addr((uint32_t)m, (uint32_t)g);
        aG0 = g_x8 + (size_t)(m0 + m) * K_TOTAL + g * 16;
        bS0 = smem + A_BYTES + swz_addr((uint32_t)m, (uint32_t)g);
        bG0 = g_wT + (size_t)(n0 + m) * K_TOTAL + g * 16;
    }

    auto load_stage = [&](int s, int chunk) {
        const uint32_t so = s * STAGE_BYTES;
        const size_t ko = (size_t)chunk * BK;
#pragma unroll
        for (int i = 0; i < 4; ++i) {
            cp_async16(aS0 + so + i * 4096u, aG0 + ko + (size_t)i * 32 * K_TOTAL);
            cp_async16(bS0 + so + i * 4096u, bG0 + ko + (size_t)i * 32 * K_TOTAL);
        }
    };

    const float scl = ascale[0] * bscale[0];

    // --- prologue: stages 0,1 ---
#pragma unroll
    for (int s = 0; s < STAGES - 1; ++s) { load_stage(s, s); cp_commit(); }

    if (warp >= 4) {
        // ========= tensor engine (hi-wid priority): cols [0, 80) =========
        const int tw = warp - 4;
        const int wm = tw >> 1;     // 0..1 (64 rows)
        const int wn = tw & 1;      // 0..1 (40 cols each)

        // A x4 (PTX ISA a0..a3): m0=r0-7 klo, m1=r8-15 klo, m2=r0-7 khi, m3=r8-15 khi
        uint32_t aOff, bOff;
        {
            const int mlocal = ((lane >> 3) & 1) * 8 + (lane & 7);
            const int k16a = lane >> 4;
            const int am = wm * 64 + mlocal;
            aOff = swz_addr((uint32_t)am, (uint32_t)k16a);
            const int j = lane >> 3;
            const int nlocal = (j >> 1) * 8 + (lane & 7);
            const int k16b = j & 1;
            const int bn = wn * 40 + nlocal;
            bOff = A_BYTES + swz_addr((uint32_t)bn, (uint32_t)k16b);
        }

        uint32_t acc[4][5][4];
#pragma unroll
        for (int mt = 0; mt < 4; ++mt)
#pragma unroll
            for (int nt = 0; nt < 5; ++nt)
#pragma unroll
                for (int r = 0; r < 4; ++r) acc[mt][nt][r] = 0;

        for (int c = 0; c < KCHUNKS; ++c) {
            cp_wait1();
            __syncthreads();
            if (c + STAGES - 1 < KCHUNKS)
                load_stage((c + STAGES - 1) % STAGES, c + STAGES - 1);
            cp_commit();

            const uint32_t so = (uint32_t)(c % STAGES) * STAGE_BYTES;
#pragma unroll
            for (int kp = 0; kp < 4; ++kp) {
                const uint32_t kx = (uint32_t)kp << 5;
                uint32_t av[4][4];
#pragma unroll
                for (int mt = 0; mt < 4; ++mt) {
                    const uint32_t ad = smem + ((aOff + so + mt * 2048u) ^ kx);
                    LDSM4(av[mt], ad);
                }
                uint32_t bv[3][4];
#pragma unroll
                for (int nt2 = 0; nt2 < 3; ++nt2) {
                    const uint32_t bd = smem + ((bOff + so + nt2 * 2048u) ^ kx);
                    LDSM4(bv[nt2], bd);
                }
#pragma unroll
                for (int mt = 0; mt < 4; ++mt)
#pragma unroll
                    for (int nt = 0; nt < 5; ++nt) {
                        const uint32_t* bp = &bv[nt >> 1][(nt & 1) * 2];
                        mma_s8(acc[mt][nt], av[mt], bp[0], bp[1]);
                    }
            }
        }

        // epilogue (tensor)
#pragma unroll
        for (int mt = 0; mt < 4; ++mt) {
#pragma unroll
            for (int nt = 0; nt < 5; ++nt) {
                const int row = m0 + wm * 64 + mt * 16 + (lane >> 2);
                const int col = n0 + wn * 40 + nt * 8 + 2 * (lane & 3);
                const int* a4 = reinterpret_cast<const int*>(acc[mt][nt]);
                float2 v0, v1;
                v0.x = (float)q8(a4[0], scl);
                v0.y = (float)q8(a4[1], scl);
                v1.x = (float)q8(a4[2], scl);
                v1.y = (float)q8(a4[3], scl);
                *reinterpret_cast<float2*>(out + (size_t)row * N_TOTAL + col) = v0;
                *reinterpret_cast<float2*>(out + (size_t)(row + 8) * N_TOTAL + col) = v1;
            }
        }
    } else {
        // ================= dp4a engine: cols [80, 128) =================
        const int r0 = warp * 32;                  // 4 row-quads of 32
        const int tr = lane >> 3;                  // 0..3 -> 8-row group
        const int tc = lane & 7;                   // 0..7 -> 6-col group

        uint32_t abase[8], bbase[6];
        uint32_t as7[8], bs7[6];
#pragma unroll
        for (int i = 0; i < 8; ++i) {
            const int r = r0 + tr * 8 + i;
            abase[i] = (uint32_t)r * 128u;
            as7[i] = (uint32_t)r & 7u;
        }
#pragma unroll
        for (int j = 0; j < 6; ++j) {
            const int n = TENSOR_N + tc * 6 + j;
            bbase[j] = A_BYTES + (uint32_t)n * 128u;
            bs7[j] = (uint32_t)n & 7u;
        }

        int accd[8][6];
#pragma unroll
        for (int i = 0; i < 8; ++i)
#pragma unroll
            for (int j = 0; j < 6; ++j) accd[i][j] = 0;

        for (int c = 0; c < KCHUNKS; ++c) {
            cp_wait1();
            __syncthreads();
            if (c + STAGES - 1 < KCHUNKS)
                load_stage((c + STAGES - 1) % STAGES, c + STAGES - 1);
            cp_commit();

            const uint32_t so = (uint32_t)(c % STAGES) * STAGE_BYTES;
#pragma unroll
            for (int g = 0; g < 8; ++g) {   // 8 x 16B k-granules
                uint4 br[6];
#pragma unroll
                for (int j = 0; j < 6; ++j)
                    br[j] = *reinterpret_cast<const uint4*>(
                        smem_raw + so + bbase[j] + ((((uint32_t)g ^ bs7[j])) << 4));
#pragma unroll
                for (int ih = 0; ih < 2; ++ih) {
                    uint4 ar[4];
#pragma unroll
                    for (int ii = 0; ii < 4; ++ii) {
                        const int i = ih * 4 + ii;
                        ar[ii] = *reinterpret_cast<const uint4*>(
                            smem_raw + so + abase[i] + ((((uint32_t)g ^ as7[i])) << 4));
                    }
#pragma unroll
                    for (int ii = 0; ii < 4; ++ii)
#pragma unroll
                        for (int j = 0; j < 6; ++j) {
                            int& a = accd[ih * 4 + ii][j];
                            a = __dp4a((int)ar[ii].x, (int)br[j].x, a);
                            a = __dp4a((int)ar[ii].y, (int)br[j].y, a);
                            a = __dp4a((int)ar[ii].z, (int)br[j].z, a);
                            a = __dp4a((int)ar[ii].w, (int)br[j].w, a);
                        }
                }
            }
        }

        // epilogue (dp4a)
#pragma unroll
        for (int i = 0; i < 8; ++i) {
            const int row = m0 + r0 + tr * 8 + i;
            const int colb = n0 + TENSOR_N + tc * 6;
#pragma unroll
            for (int jp = 0; jp < 3; ++jp) {
                float2 v;
                v.x = (float)q8(accd[i][2 * jp + 0], scl);
                v.y = (float)q8(accd[i][2 * jp + 1], scl);
                *reinterpret_cast<float2*>(out + (size_t)row * N_TOTAL + colb + 2 * jp) = v;
            }
        }
    }
}

// ============================================================================
// Launch — identify inputs by element count (robust to metadata ordering)
// ============================================================================
extern "C" void kernel_launch(void* const* d_in, const int* in_sizes, int n_in,
                              void* d_out, int out_size) {
    (void)out_size;
    const uint32_t* x = nullptr;
    const uint32_t* w = nullptr;
    const float* s1 = nullptr;
    const float* s2 = nullptr;
    for (int i = 0; i < n_in; ++i) {
        const long sz = in_sizes[i];
        if (sz == (long)M_TOTAL * K_TOTAL) x = (const uint32_t*)d_in[i];
        else if (sz == (long)K_TOTAL * N_TOTAL) w = (const uint32_t*)d_in[i];
        else if (sz == 1) { if (!s1) s1 = (const float*)d_in[i]; else s2 = (const float*)d_in[i]; }
    }
    if (!x || !w || !s1 || !s2) return;

    cudaFuncSetAttribute(w8a8_gemm_kernel,
                         cudaFuncAttributeMaxDynamicSharedMemorySize, (int)SMEM_TOTAL);

    prep_kernel<<<8192 + 4096, 256>>>(x, w);
    w8a8_gemm_kernel<<<NUM_M * NUM_N, NTHREADS, SMEM_TOTAL>>>(s1, s2, (float*)d_out);
}